// round 4
// baseline (speedup 1.0000x reference)
#include <cuda_runtime.h>
#include <cstdint>
#include <cstddef>

// Problem constants
#define BATCH  32
#define SEQ    1024
#define INDIM  128
#define HID    512
#define LAYERS 3

// Recurrence decomposition: 16 batch-groups (2 batches) x 8 j-groups (64 cols).
// The 8 j-group CTAs of one batch group form one 8-CTA cluster.
#define GB 16
#define GJ 8

// ---------------- device scratch (allocation-free rule) ------------------------
__device__ float g_P[(size_t)BATCH * SEQ * HID];   // pre-activations, current layer
__device__ float g_O[(size_t)BATCH * SEQ * HID];   // layer output sequence

// ---------------- PTX helpers --------------------------------------------------
__device__ __forceinline__ unsigned smem_u32(const void* p) {
    unsigned a;
    asm("{ .reg .u64 t; cvta.to.shared.u64 t, %1; cvt.u32.u64 %0, t; }" : "=r"(a) : "l"(p));
    return a;
}
__device__ __forceinline__ unsigned long long pack2(float x, float y) {
    unsigned long long r;
    asm("mov.b64 %0, {%1, %2};" : "=l"(r) : "f"(x), "f"(y));
    return r;
}
__device__ __forceinline__ unsigned long long ffma2(unsigned long long a,
                                                    unsigned long long b,
                                                    unsigned long long c) {
    unsigned long long d;
    asm("fma.rn.f32x2 %0, %1, %2, %3;" : "=l"(d) : "l"(a), "l"(b), "l"(c));
    return d;
}
__device__ __forceinline__ float pairsum(unsigned long long p) {
    unsigned lo, hi;
    asm("mov.b64 {%0, %1}, %2;" : "=r"(lo), "=r"(hi) : "l"(p));
    return __uint_as_float(lo) + __uint_as_float(hi);
}
__device__ __forceinline__ unsigned mapa_u32(unsigned local_addr, unsigned rank) {
    unsigned r;
    asm("mapa.shared::cluster.u32 %0, %1, %2;" : "=r"(r) : "r"(local_addr), "r"(rank));
    return r;
}
__device__ __forceinline__ void st_cluster_f32(unsigned addr, float v) {
    asm volatile("st.shared::cluster.f32 [%0], %1;" :: "r"(addr), "f"(v) : "memory");
}
__device__ __forceinline__ void mbar_init(unsigned addr, unsigned count) {
    asm volatile("mbarrier.init.shared.b64 [%0], %1;" :: "r"(addr), "r"(count) : "memory");
}
__device__ __forceinline__ void mbar_arrive_cluster(unsigned remote_addr) {
    asm volatile("mbarrier.arrive.release.cluster.shared::cluster.b64 _, [%0];"
                 :: "r"(remote_addr) : "memory");
}
__device__ __forceinline__ void mbar_wait_cluster(unsigned addr, unsigned parity) {
    unsigned done;
    asm volatile(
        "{\n\t.reg .pred p;\n\t"
        "mbarrier.try_wait.parity.acquire.cluster.shared::cta.b64 p, [%1], %2;\n\t"
        "selp.b32 %0, 1, 0, p;\n\t}"
        : "=r"(done) : "r"(addr), "r"(parity) : "memory");
    while (!done) {
        asm volatile(
            "{\n\t.reg .pred p;\n\t"
            "mbarrier.try_wait.parity.acquire.cluster.shared::cta.b64 p, [%1], %2, 0x989680;\n\t"
            "selp.b32 %0, 1, 0, p;\n\t}"
            : "=r"(done) : "r"(addr), "r"(parity) : "memory");
    }
}
__device__ __forceinline__ float ldg_f32(const float* p) {
    float v;
    asm volatile("ld.global.nc.f32 %0, [%1];" : "=f"(v) : "l"(p));
    return v;
}

// ==============================================================================
// Projection GEMM:  g_P[r][n] = sum_k A[r][k] * W[n][k] + bias[n]
// 128x128 tile, BK=8, 256 threads, 8x8 microtile. (≈fp32 peak already)
// ==============================================================================
__global__ __launch_bounds__(256) void proj_kernel(
    const float* __restrict__ Aext, int useO,
    const float* __restrict__ W,
    const float* __restrict__ bias,
    int K)
{
    const float* A = useO ? g_O : Aext;

    __shared__ float As[8][128];
    __shared__ float Bs[8][128];

    int tid = threadIdx.x;
    int m0 = blockIdx.y * 128;
    int n0 = blockIdx.x * 128;

    int lr = tid >> 1;
    int lk = (tid & 1) * 4;

    const float4* Aload = (const float4*)(A + (size_t)(m0 + lr) * K + lk);
    const float4* Wload = (const float4*)(W + (size_t)(n0 + lr) * K + lk);

    int tm = tid >> 4;
    int tn = tid & 15;

    float acc[8][8];
    #pragma unroll
    for (int i = 0; i < 8; i++)
        #pragma unroll
        for (int j = 0; j < 8; j++) acc[i][j] = 0.f;

    for (int k0 = 0; k0 < K; k0 += 8) {
        float4 av = Aload[k0 >> 2];
        float4 wv = Wload[k0 >> 2];
        As[lk + 0][lr] = av.x; As[lk + 1][lr] = av.y;
        As[lk + 2][lr] = av.z; As[lk + 3][lr] = av.w;
        Bs[lk + 0][lr] = wv.x; Bs[lk + 1][lr] = wv.y;
        Bs[lk + 2][lr] = wv.z; Bs[lk + 3][lr] = wv.w;
        __syncthreads();

        #pragma unroll
        for (int kk = 0; kk < 8; kk++) {
            float a[8], b[8];
            *(float4*)(a)     = *(const float4*)(&As[kk][tm * 8]);
            *(float4*)(a + 4) = *(const float4*)(&As[kk][tm * 8 + 4]);
            *(float4*)(b)     = *(const float4*)(&Bs[kk][tn * 8]);
            *(float4*)(b + 4) = *(const float4*)(&Bs[kk][tn * 8 + 4]);
            #pragma unroll
            for (int i = 0; i < 8; i++)
                #pragma unroll
                for (int j = 0; j < 8; j++)
                    acc[i][j] += a[i] * b[j];
        }
        __syncthreads();
    }

    float bv[8];
    #pragma unroll
    for (int j = 0; j < 8; j++) bv[j] = bias[n0 + tn * 8 + j];

    #pragma unroll
    for (int i = 0; i < 8; i++) {
        float* crow = g_P + (size_t)(m0 + tm * 8 + i) * HID + n0 + tn * 8;
        float4 v0 = make_float4(acc[i][0] + bv[0], acc[i][1] + bv[1],
                                acc[i][2] + bv[2], acc[i][3] + bv[3]);
        float4 v1 = make_float4(acc[i][4] + bv[4], acc[i][5] + bv[5],
                                acc[i][6] + bv[6], acc[i][7] + bv[7]);
        *(float4*)(crow)     = v0;
        *(float4*)(crow + 4) = v1;
    }
}

// ==============================================================================
// Persistent recurrence kernel for one layer, DSMEM-cluster h exchange.
//   h_t = tanh( g_P[b][t][:] + W_hh @ h_{t-1} + b_hh )
// Grid (GJ=8, GB=16), cluster (8,1,1): cluster rank == j-group.
// W_hh slice (64x512) in registers, packed along k for fma.rn.f32x2.
// h double-buffered in SMEM, broadcast to all 8 cluster CTAs each step,
// synced by a single phase-parity mbarrier (count 8).
// ==============================================================================
__global__ void __cluster_dims__(GJ, 1, 1) __launch_bounds__(256, 1) rec_kernel(
    const float* __restrict__ Whh,        // [512][512]
    const float* __restrict__ h0l,        // [32][512]
    const float* __restrict__ bhh,        // [512]
    float* __restrict__ out_ext, int useO,
    float* __restrict__ hidden_out)       // [32][512]
{
    float* outbuf = useO ? g_O : out_ext;

    int jg = blockIdx.x;                  // 0..7 == cluster rank
    int bg = blockIdx.y;                  // 0..15
    int b0 = bg * 2;
    int jbase = jg * 64;

    int tid = threadIdx.x;
    int w = tid >> 5;                     // warp 0..7 -> 64-wide k chunk
    int l = tid & 31;

    __shared__ float hbuf[2][2][HID];     // [phase][batch][k]
    __shared__ float red[8][2][64];       // [k-chunk][batch][jlocal]
    __shared__ float bias_sh[64];
    __shared__ __align__(8) unsigned long long bar_storage;

    unsigned bar_local = smem_u32(&bar_storage);
    unsigned hbuf_local = smem_u32(&hbuf[0][0][0]);

    if (tid == 0) mbar_init(bar_local, GJ);
    if (tid < 64) bias_sh[tid] = bhh[jbase + tid];

    // h_{-1} = h0 into phase-1 buffer (each CTA loads the full vector itself)
    #pragma unroll
    for (int i = 0; i < 4; i++) {
        int e = tid + 256 * i;
        int b = e >> 9, k = e & 511;
        hbuf[1][b][k] = h0l[(size_t)(b0 + b) * HID + k];
    }

    // W_hh slice, packed pairs along k: Wr0 -> row jbase+l, Wr1 -> row jbase+l+32
    unsigned long long Wr0[32], Wr1[32];
    {
        const float4* r0 = (const float4*)(Whh + (size_t)(jbase + l) * HID + w * 64);
        const float4* r1 = (const float4*)(Whh + (size_t)(jbase + l + 32) * HID + w * 64);
        #pragma unroll
        for (int i = 0; i < 16; i++) {
            float4 v0 = r0[i];
            Wr0[2 * i]     = pack2(v0.x, v0.y);
            Wr0[2 * i + 1] = pack2(v0.z, v0.w);
            float4 v1 = r1[i];
            Wr1[2 * i]     = pack2(v1.x, v1.y);
            Wr1[2 * i + 1] = pack2(v1.z, v1.w);
        }
    }

    // Peer addresses (DSMEM windows)
    unsigned peer_h[GJ];
    #pragma unroll
    for (int r = 0; r < GJ; r++) peer_h[r] = mapa_u32(hbuf_local, r);
    unsigned my_peer_bar = (tid < GJ) ? mapa_u32(bar_local, tid) : 0;

    __syncthreads();
    // barrier init + h0 fill visible cluster-wide before any arrives/stores
    asm volatile("barrier.cluster.arrive.aligned;" ::: "memory");
    asm volatile("barrier.cluster.wait.aligned;" ::: "memory");

    int ob = tid >> 6;                    // output batch (0/1) for tid<128
    int jl = tid & 63;                    // output column for tid<128
    const float* preptr = (tid < 128)
        ? g_P + ((size_t)(b0 + ob) * SEQ) * HID + jbase + jl : g_P;

    for (int t = 0; t < SEQ; t++) {
        // Prefetch this step's pre-activation (volatile asm keeps it above the wait)
        float pre_v = 0.f;
        if (tid < 128) pre_v = ldg_f32(preptr + (size_t)t * HID);

        // Acquire h_{t-1} (published at end of step t-1, barrier phase t-1)
        if (t > 0) mbar_wait_cluster(bar_local, (t - 1) & 1);

        int php = (t + 1) & 1;            // buffer holding h_{t-1}
        int phc = t & 1;                  // buffer for h_t

        // Partial dot products over this warp's 64-wide k chunk (f32x2 packed)
        const unsigned long long* hA =
            (const unsigned long long*)(&hbuf[php][0][w * 64]);
        const unsigned long long* hB =
            (const unsigned long long*)(&hbuf[php][1][w * 64]);
        unsigned long long a00 = 0ull, a01 = 0ull, a10 = 0ull, a11 = 0ull;
        #pragma unroll
        for (int kk = 0; kk < 32; kk++) {
            unsigned long long ha = hA[kk];   // LDS.64 broadcast
            unsigned long long hb = hB[kk];
            a00 = ffma2(Wr0[kk], ha, a00);
            a01 = ffma2(Wr0[kk], hb, a01);
            a10 = ffma2(Wr1[kk], ha, a10);
            a11 = ffma2(Wr1[kk], hb, a11);
        }
        red[w][0][l]      = pairsum(a00);
        red[w][1][l]      = pairsum(a01);
        red[w][0][l + 32] = pairsum(a10);
        red[w][1][l + 32] = pairsum(a11);
        __syncthreads();

        // Reduce 8 k-chunks, tanh, publish
        if (tid < 128) {
            float s = pre_v + bias_sh[jl];
            #pragma unroll
            for (int ww = 0; ww < 8; ww++) s += red[ww][ob][jl];
            float val = tanhf(s);

            int gb = b0 + ob;
            int gj = jbase + jl;
            outbuf[((size_t)gb * SEQ + t) * HID + gj] = val;

            if (t < SEQ - 1) {
                // Broadcast h_t slice into every cluster CTA's SMEM
                unsigned off = (unsigned)(((phc * 2 + ob) * HID + gj) * 4);
                #pragma unroll
                for (int r = 0; r < GJ; r++)
                    st_cluster_f32(peer_h[r] + off, val);
            } else {
                hidden_out[(size_t)gb * HID + gj] = val;
            }
        }
        __syncthreads();   // all DSMEM stores of this CTA done before arrives

        if (t < SEQ - 1 && tid < GJ)
            mbar_arrive_cluster(my_peer_bar);   // release: orders the stores
    }
}

// ==============================================================================
extern "C" void kernel_launch(void* const* d_in, const int* in_sizes, int n_in,
                              void* d_out, int out_size)
{
    const float* x     = (const float*)d_in[0];   // [32,1024,128]
    const float* h0    = (const float*)d_in[1];   // [3,32,512]
    const float* w_ih0 = (const float*)d_in[2];   // [512,128]
    const float* w_ihs = (const float*)d_in[3];   // [2,512,512]
    const float* w_hhs = (const float*)d_in[4];   // [3,512,512]
    const float* b_ihs = (const float*)d_in[5];   // [3,512]
    const float* b_hhs = (const float*)d_in[6];   // [3,512]

    float* out    = (float*)d_out;
    float* hidden = out;                                   // [3][32][512]
    float* outseq = out + (size_t)LAYERS * BATCH * HID;    // [32*1024][512]

    dim3 pg(HID / 128, (BATCH * SEQ) / 128);               // (4, 256)
    dim3 rg(GJ, GB);                                       // (8, 16) — 16 clusters of 8

    // ---- layer 0 ----
    proj_kernel<<<pg, 256>>>(x, 0, w_ih0, b_ihs + 0 * HID, INDIM);
    rec_kernel<<<rg, 256>>>(w_hhs + (size_t)0 * HID * HID,
                            h0 + (size_t)0 * BATCH * HID,
                            b_hhs + 0 * HID,
                            nullptr, 1,
                            hidden + (size_t)0 * BATCH * HID);
    // ---- layer 1 ----
    proj_kernel<<<pg, 256>>>(nullptr, 1, w_ihs + (size_t)0 * HID * HID,
                             b_ihs + 1 * HID, HID);
    rec_kernel<<<rg, 256>>>(w_hhs + (size_t)1 * HID * HID,
                            h0 + (size_t)1 * BATCH * HID,
                            b_hhs + 1 * HID,
                            nullptr, 1,
                            hidden + (size_t)1 * BATCH * HID);
    // ---- layer 2 (sequence straight into d_out) ----
    proj_kernel<<<pg, 256>>>(nullptr, 1, w_ihs + (size_t)1 * HID * HID,
                             b_ihs + 2 * HID, HID);
    rec_kernel<<<rg, 256>>>(w_hhs + (size_t)2 * HID * HID,
                            h0 + (size_t)2 * BATCH * HID,
                            b_hhs + 2 * HID,
                            outseq, 0,
                            hidden + (size_t)2 * BATCH * HID);
}